// round 16
// baseline (speedup 1.0000x reference)
#include <cuda_runtime.h>
#include <cuda_fp16.h>
#include <mma.h>

using namespace nvcuda;

#define NN 50000
#define EE 1600000
#define FF 128
#define D1 128       // H1*C1
#define H1c 8
#define D2 16
#define BK 128       // bucket capacity per node (P(deg>=128) ~ e^-41)

#define GEMM_BLOCKS 782             // 64 nodes each (last block partial)
#define SCAT_BLOCKS 1563            // 200000 scatter threads / 128

// ---------------- scratch (device globals; zero-initialized at load) --------
static __device__ __align__(256) __half g_W1h[FF * D1];  // fp16 W1 (kpre)
static __device__ __align__(256) __half g_h1h[NN * D1];  // 12.8 MB fp16
static __device__ __align__(256) float g_as1[NN * H1c];
static __device__ __align__(256) float g_ad1[NN * H1c];
static __device__ __align__(256) __half g_h2h[NN * D2];  // fp16 layer-2 feats
static __device__ __align__(256) float g_as2[NN];
static __device__ __align__(256) float g_ad2[NN];
static __device__ int g_cur [NN];   // invariant: all-zero at kernel_launch entry
static __device__ int g_bkt [NN * BK];                   // 25.6 MB

__device__ __forceinline__ float edgew(float e) {
    e = e > 0.f ? e : 0.2f * e;     // leaky_relu(0.2)
    return __expf(e);               // softmax shift cancels mathematically
}

// ------- KPRE: W1 fp32 -> fp16 global (4 elems/thread) ----------------------
__global__ void kpre_cvt(const float* __restrict__ W1) {
    int t = blockIdx.x * 128 + threadIdx.x;     // 32 blocks x 128 = 4096
    float4 v = ((const float4*)W1)[t];
    __half2 h0 = __floats2half2_rn(v.x, v.y);
    __half2 h1 = __floats2half2_rn(v.z, v.w);
    uint2 pk;
    pk.x = *(unsigned*)&h0;
    pk.y = *(unsigned*)&h1;
    ((uint2*)g_W1h)[t] = pk;
}

// ------- KU: fused  [blocks 0..781]   h1 = x@W1 via wmma + alphas (64 nodes)
//                    [blocks 782..]    edge scatter into buckets -------------
__global__ void ku_gemm_scatter(const float* __restrict__ x,
                                const float* __restrict__ a_src1, const float* __restrict__ a_dst1,
                                const int* __restrict__ ei) {
    __shared__ __align__(16) unsigned char smem_raw[49152];   // 48 KB exactly
    if (blockIdx.x >= GEMM_BLOCKS) {
        // -------- scatter part: 8 edges per thread --------
        int t = (blockIdx.x - GEMM_BLOCKS) * 128 + threadIdx.x;
        if (t >= EE / 8) return;
        int4 s0 = ((const int4*)ei)[t * 2];
        int4 s1 = ((const int4*)ei)[t * 2 + 1];
        int4 d0 = ((const int4*)(ei + EE))[t * 2];
        int4 d1 = ((const int4*)(ei + EE))[t * 2 + 1];
        int p0 = atomicAdd(&g_cur[d0.x], 1);
        int p1 = atomicAdd(&g_cur[d0.y], 1);
        int p2 = atomicAdd(&g_cur[d0.z], 1);
        int p3 = atomicAdd(&g_cur[d0.w], 1);
        int p4 = atomicAdd(&g_cur[d1.x], 1);
        int p5 = atomicAdd(&g_cur[d1.y], 1);
        int p6 = atomicAdd(&g_cur[d1.z], 1);
        int p7 = atomicAdd(&g_cur[d1.w], 1);
        g_bkt[d0.x * BK + (p0 & (BK - 1))] = s0.x;
        g_bkt[d0.y * BK + (p1 & (BK - 1))] = s0.y;
        g_bkt[d0.z * BK + (p2 & (BK - 1))] = s0.z;
        g_bkt[d0.w * BK + (p3 & (BK - 1))] = s0.w;
        g_bkt[d1.x * BK + (p4 & (BK - 1))] = s1.x;
        g_bkt[d1.y * BK + (p5 & (BK - 1))] = s1.y;
        g_bkt[d1.z * BK + (p6 & (BK - 1))] = s1.z;
        g_bkt[d1.w * BK + (p7 & (BK - 1))] = s1.w;
        return;
    }
    // -------- GEMM part: 64 nodes/block, wmma m16n16k16, 4 warps ------------
    __half* sWh = (__half*)smem_raw;                 // [128][128] fp16, 32KB
    __half* sX  = (__half*)(smem_raw + 32768);       // [64][128] fp16, 16KB
    float*  sO  = (float*)(smem_raw + 32768);        // [64][64] fp32 (aliases sX)
    int t = threadIdx.x;
    int w = t >> 5, lane = t & 31;
    int nb = blockIdx.x * 64;

    // stage W1 fp16 (int4 = 8 halves; 2048 int4 / 128 threads = 16 each)
    {
        const int4* src = (const int4*)g_W1h;
        int4* dst = (int4*)sWh;
#pragma unroll
        for (int i = 0; i < 16; i++) dst[t + i * 128] = __ldg(&src[t + i * 128]);
    }
    // stage x tile fp16
    for (int i = 0; i < 64; i++) {
        int n = nb + i;
        float v = (n < NN) ? x[n * FF + t] : 0.f;
        sX[i * FF + t] = __float2half(v);
    }
    __syncthreads();

    // each warp: 16-node strip m0 = w*16, all 128 cols (8 n-tiles)
    wmma::fragment<wmma::accumulator, 16, 16, 16, float> acc[8];
#pragma unroll
    for (int nt = 0; nt < 8; nt++) wmma::fill_fragment(acc[nt], 0.f);
    int m0 = w * 16;
#pragma unroll
    for (int kt = 0; kt < 8; kt++) {
        wmma::fragment<wmma::matrix_a, 16, 16, 16, __half, wmma::row_major> a;
        wmma::load_matrix_sync(a, sX + m0 * FF + kt * 16, FF);
#pragma unroll
        for (int nt = 0; nt < 8; nt++) {
            wmma::fragment<wmma::matrix_b, 16, 16, 16, __half, wmma::row_major> b;
            wmma::load_matrix_sync(b, sWh + (kt * 16) * D1 + nt * 16, D1);
            wmma::mma_sync(acc[nt], a, b, acc[nt]);
        }
    }
    __syncthreads();     // all warps done reading sX before aliasing as sO

    // two epilogue passes: cols [0,64) then [64,128)
#pragma unroll
    for (int pass = 0; pass < 2; pass++) {
        // store 4 n-tiles to sO (64x64 fp32, ld 64)
#pragma unroll
        for (int nt = 0; nt < 4; nt++)
            wmma::store_matrix_sync(sO + m0 * 64 + nt * 16, acc[pass * 4 + nt],
                                    64, wmma::mem_row_major);
        __syncthreads();
        int c = t & 63;                 // local col
        int ngrp = t >> 6;              // node half (32 nodes)
        int gc = pass * 64 + c;         // global col
        float as_c = __ldg(&a_src1[gc]);
        float ad_c = __ldg(&a_dst1[gc]);
        int head = gc >> 4;
#pragma unroll 4
        for (int j = 0; j < 32; j++) {
            int nl = ngrp * 32 + j;
            int n = nb + nl;
            float v = sO[nl * 64 + c];
            if (n < NN) g_h1h[n * D1 + gc] = __float2half(v);
            float s = v * as_c;
            float d = v * ad_c;
            s += __shfl_xor_sync(0xffffffffu, s, 1);
            s += __shfl_xor_sync(0xffffffffu, s, 2);
            s += __shfl_xor_sync(0xffffffffu, s, 4);
            s += __shfl_xor_sync(0xffffffffu, s, 8);
            d += __shfl_xor_sync(0xffffffffu, d, 1);
            d += __shfl_xor_sync(0xffffffffu, d, 2);
            d += __shfl_xor_sync(0xffffffffu, d, 4);
            d += __shfl_xor_sync(0xffffffffu, d, 8);
            if ((lane & 15) == 0 && n < NN) {
                g_as1[n * H1c + head] = s;
                g_ad1[n * H1c + head] = d;
            }
        }
        __syncthreads();
    }
}

// ------- K5: warp-per-node fused agg1 + ELU + GEMM2 + alpha2 ----------------
// 4-stage pipeline: bkt srcs 3 chunks ahead, as1 issued 2 ahead / exp'd 1
// ahead, h1 raws 1 ahead. No load consumed in its issue iteration.
__global__ void k5_agg1(const float* __restrict__ b1, const float* __restrict__ W2,
                        const float* __restrict__ as2w, const float* __restrict__ ad2w) {
    __shared__ float w2s[D1 * D2];      // 8 KB
    __shared__ float acts[8][132];
    int t = threadIdx.x;                // 256
    int warp_in = t >> 5, lane = t & 31;
    for (int i = t; i < D1 * D2; i += 256) w2s[i] = W2[i];
    __syncthreads();

    int n = blockIdx.x * 8 + warp_in;   // grid exact: 6250*8 = NN
    const int* bkt = g_bkt + n * BK;
    int deg = min(g_cur[n], BK);
    int tot = deg + 1;                  // + self loop
    int nchunk = (tot + 3) >> 2;        // warp-uniform
    int e = lane >> 3, hh = lane & 7;   // weight-duty mapping
    int h = lane >> 2;                  // head of this lane's 4 channels
    float ad_hh = __ldg(&g_ad1[n * 8 + hh]);

    // ---- prologue ----
    int i0 = e, i1 = 4 + e, i2 = 8 + e;
    int s0 = (i0 < deg) ? __ldg(&bkt[i0]) : n;
    int s1 = (i1 < deg) ? __ldg(&bkt[i1]) : n;
    int s2 = (i2 < deg) ? __ldg(&bkt[i2]) : n;
    float a0 = __ldg(&g_as1[s0 * 8 + hh]);
    float wC = (i0 < tot) ? edgew(a0 + ad_hh) : 0.f;
    float aN = __ldg(&g_as1[s1 * 8 + hh]);    // chunk 1 as1, in flight
    uint2 rawC[4];
#pragma unroll
    for (int j = 0; j < 4; j++) {
        int sj = __shfl_sync(0xffffffffu, s0, j * 8);
        rawC[j] = *(const uint2*)(g_h1h + sj * D1 + lane * 4);
    }

    float4 acc = make_float4(0.f, 0.f, 0.f, 0.f);
    float wsum = 0.f;
    for (int C = 0; C < nchunk; C++) {
        int i3 = (C + 3) * 4 + e;                     // srcs chunk C+3
        int s3 = (i3 < deg) ? __ldg(&bkt[i3]) : n;
        uint2 rawN[4];
#pragma unroll
        for (int j = 0; j < 4; j++) {                 // h1 raws chunk C+1
            int sj = __shfl_sync(0xffffffffu, s1, j * 8);
            rawN[j] = *(const uint2*)(g_h1h + sj * D1 + lane * 4);
        }
        float aCur = aN;                              // as1 chunk C+2 issue
        aN = __ldg(&g_as1[s2 * 8 + hh]);
        int iN = (C + 1) * 4 + e;                     // exp chunk C+1
        float wN = (iN < tot) ? edgew(aCur + ad_hh) : 0.f;
        wsum += wC;                                   // consume chunk C
#pragma unroll
        for (int j = 0; j < 4; j++) {
            float al = __shfl_sync(0xffffffffu, wC, j * 8 + h);
            float2 f0 = __half22float2(*(__half2*)&rawC[j].x);
            float2 f1 = __half22float2(*(__half2*)&rawC[j].y);
            acc.x = fmaf(al, f0.x, acc.x);
            acc.y = fmaf(al, f0.y, acc.y);
            acc.z = fmaf(al, f1.x, acc.z);
            acc.w = fmaf(al, f1.y, acc.w);
        }
        wC = wN;
        s1 = s2; s2 = s3;
#pragma unroll
        for (int j = 0; j < 4; j++) rawC[j] = rawN[j];
    }
    wsum += __shfl_xor_sync(0xffffffffu, wsum, 8);
    wsum += __shfl_xor_sync(0xffffffffu, wsum, 16);
    float inv = 1.f / __shfl_sync(0xffffffffu, wsum, h);

    int c0 = lane * 4;
    float4 v;
    v.x = acc.x * inv + __ldg(&b1[c0 + 0]);
    v.y = acc.y * inv + __ldg(&b1[c0 + 1]);
    v.z = acc.z * inv + __ldg(&b1[c0 + 2]);
    v.w = acc.w * inv + __ldg(&b1[c0 + 3]);
    v.x = v.x > 0.f ? v.x : (__expf(v.x) - 1.f);
    v.y = v.y > 0.f ? v.y : (__expf(v.y) - 1.f);
    v.z = v.z > 0.f ? v.z : (__expf(v.z) - 1.f);
    v.w = v.w > 0.f ? v.w : (__expf(v.w) - 1.f);
    *(float4*)&acts[warp_in][c0] = v;
    __syncwarp();

    // GEMM2 128->16
    int c = lane & 15, k0 = (lane >> 4) * 64;
    float p = 0.f;
#pragma unroll 16
    for (int k = 0; k < 64; k++)
        p = fmaf(acts[warp_in][k0 + k], w2s[(k0 + k) * D2 + c], p);
    p += __shfl_xor_sync(0xffffffffu, p, 16);
    if (lane < 16) g_h2h[n * D2 + lane] = __float2half(p);
    float sa = p * __ldg(&as2w[c]);
    float sd = p * __ldg(&ad2w[c]);
#pragma unroll
    for (int o = 8; o; o >>= 1) {
        sa += __shfl_xor_sync(0xffffffffu, sa, o);
        sd += __shfl_xor_sync(0xffffffffu, sd, o);
    }
    if (lane == 0) { g_as2[n] = sa; g_ad2[n] = sd; }
}

// ------- K6: warp-per-node layer-2 agg; fp16 h2 quad gather; re-zero g_cur --
__global__ void k6_agg2(const float* __restrict__ b2, float* __restrict__ out) {
    int warp = (blockIdx.x * blockDim.x + threadIdx.x) >> 5;
    int lane = threadIdx.x & 31;
    int n = warp;                       // grid exact
    const int* bkt = g_bkt + n * BK;
    int deg = min(g_cur[n], BK);
    int tot = deg + 1;
    float ad2n = g_ad2[n];
    int q = lane & 3, g = lane >> 2;    // channel-quad, edge-group
    float4 acc = make_float4(0.f, 0.f, 0.f, 0.f);
    float wacc = 0.f;
    for (int base = 0; base < tot; base += 32) {      // trip warp-uniform
        int i = base + lane;
        int s = (i < deg) ? __ldg(&bkt[i]) : n;       // 1 edge per lane
        float w = 0.f;
        if (i < tot) w = edgew(__ldg(&g_as2[s]) + ad2n);
        wacc += w;
        int m = min(tot - base, 32);                  // warp-uniform
        for (int j = 0; j < m; j += 8) {              // 8 edges per step
            int jj = j + g;                           // w=0 on padded lanes
            float wj = __shfl_sync(0xffffffffu, w, jj);
            int   sj = __shfl_sync(0xffffffffu, s, jj);
            uint2 raw = *(const uint2*)(g_h2h + sj * D2 + q * 4);
            float2 h0 = __half22float2(*(__half2*)&raw.x);
            float2 h1 = __half22float2(*(__half2*)&raw.y);
            acc.x = fmaf(wj, h0.x, acc.x);
            acc.y = fmaf(wj, h0.y, acc.y);
            acc.z = fmaf(wj, h1.x, acc.z);
            acc.w = fmaf(wj, h1.y, acc.w);
        }
    }
#pragma unroll
    for (int o = 4; o <= 16; o <<= 1) {
        acc.x += __shfl_xor_sync(0xffffffffu, acc.x, o);
        acc.y += __shfl_xor_sync(0xffffffffu, acc.y, o);
        acc.z += __shfl_xor_sync(0xffffffffu, acc.z, o);
        acc.w += __shfl_xor_sync(0xffffffffu, acc.w, o);
    }
#pragma unroll
    for (int o = 16; o; o >>= 1) wacc += __shfl_xor_sync(0xffffffffu, wacc, o);
    if (lane < 4) {
        float invw = 1.f / wacc;
        float4 bv = *(const float4*)(b2 + q * 4);
        float4 r;
        r.x = acc.x * invw + bv.x;
        r.y = acc.y * invw + bv.y;
        r.z = acc.z * invw + bv.z;
        r.w = acc.w * invw + bv.w;
        *(float4*)(out + n * D2 + q * 4) = r;
    }
    if (lane == 0) g_cur[n] = 0;        // restore entry invariant for next call
}

// ---------------- launch ----------------
extern "C" void kernel_launch(void* const* d_in, const int* in_sizes, int n_in,
                              void* d_out, int out_size) {
    const float* x      = (const float*)d_in[0];
    const int*   ei     = (const int*)  d_in[1];
    const float* W1     = (const float*)d_in[2];
    const float* a_src1 = (const float*)d_in[3];
    const float* a_dst1 = (const float*)d_in[4];
    const float* b1     = (const float*)d_in[5];
    const float* W2     = (const float*)d_in[6];
    const float* a_src2 = (const float*)d_in[7];
    const float* a_dst2 = (const float*)d_in[8];
    const float* b2     = (const float*)d_in[9];
    float* out = (float*)d_out;

    kpre_cvt       <<<32, 128>>>(W1);
    ku_gemm_scatter<<<GEMM_BLOCKS + SCAT_BLOCKS, 128>>>(x, a_src1, a_dst1, ei);
    k5_agg1        <<<NN / 8, 256>>>(b1, W2, a_src2, a_dst2);
    k6_agg2        <<<NN / 8, 256>>>(b2, out);
}

// round 17
// speedup vs baseline: 1.1596x; 1.1596x over previous
#include <cuda_runtime.h>
#include <cuda_fp16.h>
#include <mma.h>

using namespace nvcuda;

#define NN 50000
#define EE 1600000
#define FF 128
#define D1 128       // H1*C1
#define H1c 8
#define D2 16
#define BK 128       // bucket capacity per node (P(deg>=128) ~ e^-41)
#define DW 144       // augmented GEMM width: 128 h1 + 8 as + 8 ad

#define NT 48                         // nodes per GEMM block
#define GEMM_BLOCKS 1042              // ceil(50000/48)
#define SCAT_BLOCKS 1563              // 200000 scatter threads / 128

// ---------------- scratch (device globals; zero-initialized at load) --------
static __device__ __align__(256) __half g_Wxh[FF * DW];  // [W1 | As | Ad] fp16
static __device__ __align__(256) __half g_h1h[NN * D1];  // 12.8 MB fp16
static __device__ __align__(256) float g_as1[NN * H1c];
static __device__ __align__(256) float g_ad1[NN * H1c];
static __device__ __align__(256) __half g_h2h[NN * D2];  // fp16 layer-2 feats
static __device__ __align__(256) float g_as2[NN];
static __device__ __align__(256) float g_ad2[NN];
static __device__ int g_cur [NN];   // invariant: all-zero at kernel_launch entry
static __device__ int g_bkt [NN * BK];                   // 25.6 MB

__device__ __forceinline__ float edgew(float e) {
    e = e > 0.f ? e : 0.2f * e;     // leaky_relu(0.2)
    return __expf(e);               // softmax shift cancels mathematically
}

// ------- KPRE: build augmented fp16 weights [W1 | As | Ad] ------------------
// warp per row k: lane holds 4 cols (one head-quad); As[k][h]=sum_c W1*a_src
__global__ void kpre_build(const float* __restrict__ W1,
                           const float* __restrict__ as, const float* __restrict__ ad) {
    int warp = blockIdx.x * 4 + (threadIdx.x >> 5);   // 32 blocks x 4 warps = 128 rows
    int lane = threadIdx.x & 31;
    int k = warp;
    float4 w4 = __ldg((const float4*)&W1[k * 128 + lane * 4]);
    __half2 p0 = __floats2half2_rn(w4.x, w4.y);
    __half2 p1 = __floats2half2_rn(w4.z, w4.w);
    uint2 pk;
    pk.x = *(unsigned*)&p0;
    pk.y = *(unsigned*)&p1;
    *(uint2*)&g_Wxh[k * DW + lane * 4] = pk;
    float4 a4 = __ldg((const float4*)&as[lane * 4]);
    float4 d4 = __ldg((const float4*)&ad[lane * 4]);
    float sa = w4.x * a4.x + w4.y * a4.y + w4.z * a4.z + w4.w * a4.w;
    float sd = w4.x * d4.x + w4.y * d4.y + w4.z * d4.z + w4.w * d4.w;
    sa += __shfl_xor_sync(0xffffffffu, sa, 1);
    sa += __shfl_xor_sync(0xffffffffu, sa, 2);
    sd += __shfl_xor_sync(0xffffffffu, sd, 1);
    sd += __shfl_xor_sync(0xffffffffu, sd, 2);
    float va = __shfl_sync(0xffffffffu, sa, (lane & 7) * 4);   // head (lane&7) sum
    float vd = __shfl_sync(0xffffffffu, sd, (lane & 7) * 4);
    if (lane < 8)       g_Wxh[k * DW + 128 + lane] = __float2half(va);
    else if (lane < 16) g_Wxh[k * DW + 136 + (lane - 8)] = __float2half(vd);
}

// ------- KU: fused  [blocks 0..1041]  Z = x @ Wx via wmma (48 nodes/block)
//                    [blocks 1042..]   edge scatter into buckets -------------
__global__ void ku_gemm_scatter(const float* __restrict__ x,
                                const int* __restrict__ ei) {
    __shared__ __align__(16) unsigned char smem_raw[49152];   // 48 KB exactly
    if (blockIdx.x >= GEMM_BLOCKS) {
        // -------- scatter part: 8 edges per thread --------
        int t = (blockIdx.x - GEMM_BLOCKS) * 128 + threadIdx.x;
        if (t >= EE / 8) return;
        int4 s0 = ((const int4*)ei)[t * 2];
        int4 s1 = ((const int4*)ei)[t * 2 + 1];
        int4 d0 = ((const int4*)(ei + EE))[t * 2];
        int4 d1 = ((const int4*)(ei + EE))[t * 2 + 1];
        int p0 = atomicAdd(&g_cur[d0.x], 1);
        int p1 = atomicAdd(&g_cur[d0.y], 1);
        int p2 = atomicAdd(&g_cur[d0.z], 1);
        int p3 = atomicAdd(&g_cur[d0.w], 1);
        int p4 = atomicAdd(&g_cur[d1.x], 1);
        int p5 = atomicAdd(&g_cur[d1.y], 1);
        int p6 = atomicAdd(&g_cur[d1.z], 1);
        int p7 = atomicAdd(&g_cur[d1.w], 1);
        g_bkt[d0.x * BK + (p0 & (BK - 1))] = s0.x;
        g_bkt[d0.y * BK + (p1 & (BK - 1))] = s0.y;
        g_bkt[d0.z * BK + (p2 & (BK - 1))] = s0.z;
        g_bkt[d0.w * BK + (p3 & (BK - 1))] = s0.w;
        g_bkt[d1.x * BK + (p4 & (BK - 1))] = s1.x;
        g_bkt[d1.y * BK + (p5 & (BK - 1))] = s1.y;
        g_bkt[d1.z * BK + (p6 & (BK - 1))] = s1.z;
        g_bkt[d1.w * BK + (p7 & (BK - 1))] = s1.w;
        return;
    }
    // -------- GEMM part: 48 nodes/block, wmma m16n16k16 ---------------------
    __half* sW = (__half*)smem_raw;                  // [128][144] fp16, 36864B
    __half* sX = (__half*)(smem_raw + 36864);        // [48][128] fp16, 12288B
    float*  sO = (float*)smem_raw;                   // [48][144] f32 (aliases sW)
    int t = threadIdx.x;
    int w = t >> 5;
    int nb = blockIdx.x * NT;

    // stage Wx (2304 int4 / 128 threads = 18 each)
    {
        const int4* src = (const int4*)g_Wxh;
        int4* dst = (int4*)sW;
#pragma unroll
        for (int i = 0; i < 18; i++) dst[t + i * 128] = __ldg(&src[t + i * 128]);
    }
    // stage x tile fp16
#pragma unroll 4
    for (int i = 0; i < NT; i++) {
        int n = nb + i;
        float v = (n < NN) ? x[n * FF + t] : 0.f;
        sX[i * FF + t] = __float2half(v);
    }
    __syncthreads();

    // warps 0..2: 16-node strip each, 9 n-tiles of 16 cols
    wmma::fragment<wmma::accumulator, 16, 16, 16, float> acc[9];
    int m0 = w * 16;
    if (w < 3) {
#pragma unroll
        for (int nt = 0; nt < 9; nt++) wmma::fill_fragment(acc[nt], 0.f);
#pragma unroll
        for (int kt = 0; kt < 8; kt++) {
            wmma::fragment<wmma::matrix_a, 16, 16, 16, __half, wmma::row_major> a;
            wmma::load_matrix_sync(a, sX + m0 * FF + kt * 16, FF);
#pragma unroll
            for (int nt = 0; nt < 9; nt++) {
                wmma::fragment<wmma::matrix_b, 16, 16, 16, __half, wmma::row_major> b;
                wmma::load_matrix_sync(b, sW + (kt * 16) * DW + nt * 16, DW);
                wmma::mma_sync(acc[nt], a, b, acc[nt]);
            }
        }
    }
    __syncthreads();     // all reads of sW/sX complete before aliasing as sO
    if (w < 3) {
#pragma unroll
        for (int nt = 0; nt < 9; nt++)
            wmma::store_matrix_sync(sO + m0 * DW + nt * 16, acc[nt],
                                    DW, wmma::mem_row_major);
    }
    __syncthreads();

    // copy-out h1 (cols 0..127) as half2, coalesced
    int c2 = (t & 63) * 2;
    int rh = t >> 6;
#pragma unroll 4
    for (int j = 0; j < 24; j++) {
        int row = rh * 24 + j;
        int n = nb + row;
        if (n < NN) {
            __half2 hv = __floats2half2_rn(sO[row * DW + c2], sO[row * DW + c2 + 1]);
            *(unsigned*)&g_h1h[n * D1 + c2] = *(unsigned*)&hv;
        }
    }
    // copy-out alphas (cols 128..143), f32
#pragma unroll
    for (int i = t; i < NT * 16; i += 128) {
        int row = i >> 4, idx = i & 15;
        int n = nb + row;
        if (n < NN) {
            float v = sO[row * DW + 128 + idx];
            if (idx < 8) g_as1[n * H1c + idx] = v;
            else         g_ad1[n * H1c + idx - 8] = v;
        }
    }
}

// ------- K5: warp-per-node fused agg1 + ELU + GEMM2 + alpha2 ----------------
// 4-stage pipeline: bkt srcs 3 chunks ahead, as1 issued 2 ahead / exp'd 1
// ahead, h1 raws 1 ahead. No load consumed in its issue iteration.
__global__ void k5_agg1(const float* __restrict__ b1, const float* __restrict__ W2,
                        const float* __restrict__ as2w, const float* __restrict__ ad2w) {
    __shared__ float w2s[D1 * D2];      // 8 KB
    __shared__ float acts[8][132];
    int t = threadIdx.x;                // 256
    int warp_in = t >> 5, lane = t & 31;
    for (int i = t; i < D1 * D2; i += 256) w2s[i] = W2[i];
    __syncthreads();

    int n = blockIdx.x * 8 + warp_in;   // grid exact: 6250*8 = NN
    const int* bkt = g_bkt + n * BK;
    int deg = min(g_cur[n], BK);
    int tot = deg + 1;                  // + self loop
    int nchunk = (tot + 3) >> 2;        // warp-uniform
    int e = lane >> 3, hh = lane & 7;   // weight-duty mapping
    int h = lane >> 2;                  // head of this lane's 4 channels
    float ad_hh = __ldg(&g_ad1[n * 8 + hh]);

    // ---- prologue ----
    int i0 = e, i1 = 4 + e, i2 = 8 + e;
    int s0 = (i0 < deg) ? __ldg(&bkt[i0]) : n;
    int s1 = (i1 < deg) ? __ldg(&bkt[i1]) : n;
    int s2 = (i2 < deg) ? __ldg(&bkt[i2]) : n;
    float a0 = __ldg(&g_as1[s0 * 8 + hh]);
    float wC = (i0 < tot) ? edgew(a0 + ad_hh) : 0.f;
    float aN = __ldg(&g_as1[s1 * 8 + hh]);    // chunk 1 as1, in flight
    uint2 rawC[4];
#pragma unroll
    for (int j = 0; j < 4; j++) {
        int sj = __shfl_sync(0xffffffffu, s0, j * 8);
        rawC[j] = *(const uint2*)(g_h1h + sj * D1 + lane * 4);
    }

    float4 acc = make_float4(0.f, 0.f, 0.f, 0.f);
    float wsum = 0.f;
    for (int C = 0; C < nchunk; C++) {
        int i3 = (C + 3) * 4 + e;                     // srcs chunk C+3
        int s3 = (i3 < deg) ? __ldg(&bkt[i3]) : n;
        uint2 rawN[4];
#pragma unroll
        for (int j = 0; j < 4; j++) {                 // h1 raws chunk C+1
            int sj = __shfl_sync(0xffffffffu, s1, j * 8);
            rawN[j] = *(const uint2*)(g_h1h + sj * D1 + lane * 4);
        }
        float aCur = aN;                              // as1 chunk C+2 issue
        aN = __ldg(&g_as1[s2 * 8 + hh]);
        int iN = (C + 1) * 4 + e;                     // exp chunk C+1
        float wN = (iN < tot) ? edgew(aCur + ad_hh) : 0.f;
        wsum += wC;                                   // consume chunk C
#pragma unroll
        for (int j = 0; j < 4; j++) {
            float al = __shfl_sync(0xffffffffu, wC, j * 8 + h);
            float2 f0 = __half22float2(*(__half2*)&rawC[j].x);
            float2 f1 = __half22float2(*(__half2*)&rawC[j].y);
            acc.x = fmaf(al, f0.x, acc.x);
            acc.y = fmaf(al, f0.y, acc.y);
            acc.z = fmaf(al, f1.x, acc.z);
            acc.w = fmaf(al, f1.y, acc.w);
        }
        wC = wN;
        s1 = s2; s2 = s3;
#pragma unroll
        for (int j = 0; j < 4; j++) rawC[j] = rawN[j];
    }
    wsum += __shfl_xor_sync(0xffffffffu, wsum, 8);
    wsum += __shfl_xor_sync(0xffffffffu, wsum, 16);
    float inv = 1.f / __shfl_sync(0xffffffffu, wsum, h);

    int c0 = lane * 4;
    float4 v;
    v.x = acc.x * inv + __ldg(&b1[c0 + 0]);
    v.y = acc.y * inv + __ldg(&b1[c0 + 1]);
    v.z = acc.z * inv + __ldg(&b1[c0 + 2]);
    v.w = acc.w * inv + __ldg(&b1[c0 + 3]);
    v.x = v.x > 0.f ? v.x : (__expf(v.x) - 1.f);
    v.y = v.y > 0.f ? v.y : (__expf(v.y) - 1.f);
    v.z = v.z > 0.f ? v.z : (__expf(v.z) - 1.f);
    v.w = v.w > 0.f ? v.w : (__expf(v.w) - 1.f);
    *(float4*)&acts[warp_in][c0] = v;
    __syncwarp();

    // GEMM2 128->16
    int c = lane & 15, k0 = (lane >> 4) * 64;
    float p = 0.f;
#pragma unroll 16
    for (int k = 0; k < 64; k++)
        p = fmaf(acts[warp_in][k0 + k], w2s[(k0 + k) * D2 + c], p);
    p += __shfl_xor_sync(0xffffffffu, p, 16);
    if (lane < 16) g_h2h[n * D2 + lane] = __float2half(p);
    float sa = p * __ldg(&as2w[c]);
    float sd = p * __ldg(&ad2w[c]);
#pragma unroll
    for (int o = 8; o; o >>= 1) {
        sa += __shfl_xor_sync(0xffffffffu, sa, o);
        sd += __shfl_xor_sync(0xffffffffu, sd, o);
    }
    if (lane == 0) { g_as2[n] = sa; g_ad2[n] = sd; }
}

// ------- K6: warp-per-node layer-2 agg; fp16 h2 quad gather; re-zero g_cur --
__global__ void k6_agg2(const float* __restrict__ b2, float* __restrict__ out) {
    int warp = (blockIdx.x * blockDim.x + threadIdx.x) >> 5;
    int lane = threadIdx.x & 31;
    int n = warp;                       // grid exact
    const int* bkt = g_bkt + n * BK;
    int deg = min(g_cur[n], BK);
    int tot = deg + 1;
    float ad2n = g_ad2[n];
    int q = lane & 3, g = lane >> 2;    // channel-quad, edge-group
    float4 acc = make_float4(0.f, 0.f, 0.f, 0.f);
    float wacc = 0.f;
    for (int base = 0; base < tot; base += 32) {      // trip warp-uniform
        int i = base + lane;
        int s = (i < deg) ? __ldg(&bkt[i]) : n;       // 1 edge per lane
        float w = 0.f;
        if (i < tot) w = edgew(__ldg(&g_as2[s]) + ad2n);
        wacc += w;
        int m = min(tot - base, 32);                  // warp-uniform
        for (int j = 0; j < m; j += 8) {              // 8 edges per step
            int jj = j + g;                           // w=0 on padded lanes
            float wj = __shfl_sync(0xffffffffu, w, jj);
            int   sj = __shfl_sync(0xffffffffu, s, jj);
            uint2 raw = *(const uint2*)(g_h2h + sj * D2 + q * 4);
            float2 h0 = __half22float2(*(__half2*)&raw.x);
            float2 h1 = __half22float2(*(__half2*)&raw.y);
            acc.x = fmaf(wj, h0.x, acc.x);
            acc.y = fmaf(wj, h0.y, acc.y);
            acc.z = fmaf(wj, h1.x, acc.z);
            acc.w = fmaf(wj, h1.y, acc.w);
        }
    }
#pragma unroll
    for (int o = 4; o <= 16; o <<= 1) {
        acc.x += __shfl_xor_sync(0xffffffffu, acc.x, o);
        acc.y += __shfl_xor_sync(0xffffffffu, acc.y, o);
        acc.z += __shfl_xor_sync(0xffffffffu, acc.z, o);
        acc.w += __shfl_xor_sync(0xffffffffu, acc.w, o);
    }
#pragma unroll
    for (int o = 16; o; o >>= 1) wacc += __shfl_xor_sync(0xffffffffu, wacc, o);
    if (lane < 4) {
        float invw = 1.f / wacc;
        float4 bv = *(const float4*)(b2 + q * 4);
        float4 r;
        r.x = acc.x * invw + bv.x;
        r.y = acc.y * invw + bv.y;
        r.z = acc.z * invw + bv.z;
        r.w = acc.w * invw + bv.w;
        *(float4*)(out + n * D2 + q * 4) = r;
    }
    if (lane == 0) g_cur[n] = 0;        // restore entry invariant for next call
}

// ---------------- launch ----------------
extern "C" void kernel_launch(void* const* d_in, const int* in_sizes, int n_in,
                              void* d_out, int out_size) {
    const float* x      = (const float*)d_in[0];
    const int*   ei     = (const int*)  d_in[1];
    const float* W1     = (const float*)d_in[2];
    const float* a_src1 = (const float*)d_in[3];
    const float* a_dst1 = (const float*)d_in[4];
    const float* b1     = (const float*)d_in[5];
    const float* W2     = (const float*)d_in[6];
    const float* a_src2 = (const float*)d_in[7];
    const float* a_dst2 = (const float*)d_in[8];
    const float* b2     = (const float*)d_in[9];
    float* out = (float*)d_out;

    kpre_build     <<<32, 128>>>(W1, a_src1, a_dst1);
    ku_gemm_scatter<<<GEMM_BLOCKS + SCAT_BLOCKS, 128>>>(x, ei);
    k5_agg1        <<<NN / 8, 256>>>(b1, W2, a_src2, a_dst2);
    k6_agg2        <<<NN / 8, 256>>>(b2, out);
}